// round 3
// baseline (speedup 1.0000x reference)
#include <cuda_runtime.h>
#include <math.h>

// ---------------- problem constants ----------------
#define BB   2
#define SS   4096
#define DDIM 768
#define HH   12
#define DH   64
#define NB   64          // S / BLK
#define LL   2
#define MM   (BB*SS)     // 8192 tokens
#define FF   (4*DDIM)    // 3072

// ---------------- persistent scratch (no runtime allocs allowed) ----------------
__device__ float g_x  [MM*DDIM];
__device__ float g_q  [MM*DDIM];
__device__ float g_k  [MM*DDIM];
__device__ float g_v  [MM*DDIM];
__device__ float g_t  [MM*DDIM];
__device__ float g_ffh[MM*FF];

// ---------------- helpers ----------------
__device__ __forceinline__ float2 blockReduce2(float a, float b) {
    __shared__ float sbuf[64];
    const unsigned FULLM = 0xffffffffu;
#pragma unroll
    for (int o = 16; o > 0; o >>= 1) {
        a += __shfl_down_sync(FULLM, a, o);
        b += __shfl_down_sync(FULLM, b, o);
    }
    int warp = threadIdx.x >> 5;
    int nw   = (blockDim.x + 31) >> 5;
    if ((threadIdx.x & 31) == 0) { sbuf[warp] = a; sbuf[32 + warp] = b; }
    __syncthreads();
    if (threadIdx.x == 0) {
        float ta = 0.f, tb = 0.f;
        for (int i = 0; i < nw; i++) { ta += sbuf[i]; tb += sbuf[32 + i]; }
        sbuf[0] = ta; sbuf[32] = tb;
    }
    __syncthreads();
    return make_float2(sbuf[0], sbuf[32]);
}

__device__ __forceinline__ float gelu_tanh(float x) {
    float x3 = x * x * x;
    return 0.5f * x * (1.f + tanhf(0.79788456080286535588f * (x + 0.044715f * x3)));
}

// ---------------- embedding + LN ----------------
__global__ void embed_ln_kernel(const int* __restrict__ ids,
                                const float* __restrict__ emb_tok,
                                const float* __restrict__ emb_pos,
                                const float* __restrict__ g,
                                const float* __restrict__ bta,
                                float* __restrict__ x) {
    int token = blockIdx.x;          // 0..MM-1
    int s = token & (SS - 1);
    int id = ids[token];
    const float* et = emb_tok + (size_t)id * DDIM;
    const float* ep = emb_pos + (size_t)s * DDIM;
    float vals[3];
    float sum = 0.f, sq = 0.f;
#pragma unroll
    for (int i = 0; i < 3; i++) {
        int d = threadIdx.x + i * 256;
        float vv = et[d] + ep[d];
        vals[i] = vv; sum += vv; sq += vv * vv;
    }
    float2 r = blockReduce2(sum, sq);
    float mean = r.x * (1.f / DDIM);
    float var  = r.y * (1.f / DDIM) - mean * mean;
    float rstd = rsqrtf(var + 1e-12f);
    float* xr = x + (size_t)token * DDIM;
#pragma unroll
    for (int i = 0; i < 3; i++) {
        int d = threadIdx.x + i * 256;
        xr[d] = (vals[i] - mean) * rstd * g[d] + bta[d];
    }
}

// ---------------- residual add + LN (in-place on x) ----------------
__global__ void add_ln_kernel(float* __restrict__ x,
                              const float* __restrict__ y,
                              const float* __restrict__ g,
                              const float* __restrict__ bta) {
    int token = blockIdx.x;
    float* xr = x + (size_t)token * DDIM;
    const float* yr = y + (size_t)token * DDIM;
    float vals[3];
    float sum = 0.f, sq = 0.f;
#pragma unroll
    for (int i = 0; i < 3; i++) {
        int d = threadIdx.x + i * 256;
        float vv = xr[d] + yr[d];
        vals[i] = vv; sum += vv; sq += vv * vv;
    }
    float2 r = blockReduce2(sum, sq);
    float mean = r.x * (1.f / DDIM);
    float var  = r.y * (1.f / DDIM) - mean * mean;
    float rstd = rsqrtf(var + 1e-12f);
#pragma unroll
    for (int i = 0; i < 3; i++) {
        int d = threadIdx.x + i * 256;
        xr[d] = (vals[i] - mean) * rstd * g[d] + bta[d];
    }
}

// ---------------- SGEMM: C[M,N] = A[M,Kd] @ W[Kd,N] + bias (optional GELU) ----------
// BM=128, BN=64, BK=16, 256 threads, 8x4 micro-tile. M%128==0, N%64==0, Kd%16==0.
template <int DO_GELU>
__global__ void __launch_bounds__(256, 2)
gemm_kernel(const float* __restrict__ A, const float* __restrict__ W,
            const float* __restrict__ bias, float* __restrict__ C,
            int N, int Kd) {
    const int BM = 128, BN = 64, BK = 16;
    __shared__ float As[BK][BM + 4];   // transposed A tile, +4 pad
    __shared__ float Bs[BK][BN];
    int tid = threadIdx.x;
    int tx = tid & 15, ty = tid >> 4;
    const int m0 = blockIdx.y * BM, n0 = blockIdx.x * BN;
    float acc[8][4];
#pragma unroll
    for (int i = 0; i < 8; i++)
#pragma unroll
        for (int j = 0; j < 4; j++) acc[i][j] = 0.f;

    const float* Aptr = A + (size_t)m0 * Kd;
    const float* Wptr = W + n0;
    const int arow = tid >> 2;
    const int acol = (tid & 3) * 4;
    const int brow = tid >> 4;
    const int bcol = (tid & 15) * 4;

    for (int k0 = 0; k0 < Kd; k0 += BK) {
#pragma unroll
        for (int rr = 0; rr < 2; rr++) {
            float4 av = *reinterpret_cast<const float4*>(
                Aptr + (size_t)(arow + rr * 64) * Kd + k0 + acol);
            As[acol + 0][arow + rr * 64] = av.x;
            As[acol + 1][arow + rr * 64] = av.y;
            As[acol + 2][arow + rr * 64] = av.z;
            As[acol + 3][arow + rr * 64] = av.w;
        }
        *reinterpret_cast<float4*>(&Bs[brow][bcol]) =
            *reinterpret_cast<const float4*>(Wptr + (size_t)(k0 + brow) * N + bcol);
        __syncthreads();
#pragma unroll
        for (int kk = 0; kk < BK; kk++) {
            float a[8], b[4];
#pragma unroll
            for (int i = 0; i < 2; i++) {
                float4 t = *reinterpret_cast<const float4*>(&As[kk][ty * 8 + i * 4]);
                a[i*4+0] = t.x; a[i*4+1] = t.y; a[i*4+2] = t.z; a[i*4+3] = t.w;
            }
            float4 tb = *reinterpret_cast<const float4*>(&Bs[kk][tx * 4]);
            b[0] = tb.x; b[1] = tb.y; b[2] = tb.z; b[3] = tb.w;
#pragma unroll
            for (int i = 0; i < 8; i++)
#pragma unroll
                for (int j = 0; j < 4; j++)
                    acc[i][j] = fmaf(a[i], b[j], acc[i][j]);
        }
        __syncthreads();
    }
    float4 bv = *reinterpret_cast<const float4*>(bias + n0 + tx * 4);
    float bb[4] = {bv.x, bv.y, bv.z, bv.w};
#pragma unroll
    for (int i = 0; i < 8; i++) {
        int row = m0 + ty * 8 + i;
        float4 o;
        o.x = acc[i][0] + bb[0];
        o.y = acc[i][1] + bb[1];
        o.z = acc[i][2] + bb[2];
        o.w = acc[i][3] + bb[3];
        if (DO_GELU) {
            o.x = gelu_tanh(o.x); o.y = gelu_tanh(o.y);
            o.z = gelu_tanh(o.z); o.w = gelu_tanh(o.w);
        }
        *reinterpret_cast<float4*>(C + (size_t)row * N + n0 + tx * 4) = o;
    }
}

// ---------------- BigBird attention (online softmax) ----------------
// grid (NB, HH, BB), 256 threads. Each CTA: one (batch, head, query-block).
// Query blocks 0 and NB-1 do full attention (64 key blocks); others the 8
// gathered blocks [0, i-1, i, i+1, NB-1, r0, r1, r2] (duplicates preserved).
// Thread t: query row r = t/4, key/dim group c = t%4 (16 keys or 16 dims).
__global__ void __launch_bounds__(256)
attn_kernel(const float* __restrict__ q, const float* __restrict__ k,
            const float* __restrict__ v, const int* __restrict__ rand_blocks,
            float* __restrict__ o) {
    extern __shared__ float sm[];
    float* qs = sm;                  // 64 x 65
    float* ks = qs + 64 * 65;        // 64 x 65
    float* vs = ks + 64 * 65;        // 64 x 64 (float4-aligned)
    float* ps = vs + 64 * 64;        // 64 x 65

    int qb = blockIdx.x, h = blockIdx.y, b = blockIdx.z;
    int tid = threadIdx.x;
    size_t qbase = ((size_t)b * SS + qb * 64) * DDIM + h * 64;

    for (int i = tid; i < 4096; i += 256) {
        int r = i >> 6, d = i & 63;
        qs[r * 65 + d] = q[qbase + (size_t)r * DDIM + d];
    }
    bool full = (qb == 0) || (qb == NB - 1);
    int nkb = full ? 64 : 8;
    int list[8] = {0,0,0,0,0,0,0,0};
    if (!full) {
        list[0] = 0; list[1] = qb - 1; list[2] = qb;
        list[3] = qb + 1; list[4] = NB - 1;
        const int* rb = rand_blocks + ((size_t)h * NB + qb) * 3;
        list[5] = rb[0]; list[6] = rb[1]; list[7] = rb[2];
    }
    __syncthreads();

    int r = tid >> 2, c = tid & 3;
    float mrun = -1e30f, lrun = 0.f;
    float ctx[16];
#pragma unroll
    for (int i = 0; i < 16; i++) ctx[i] = 0.f;

    const float* qrow  = qs + r * 65;
    const float* kbase = ks + c * 16 * 65;
    float* prow        = ps + r * 65;
    const float4* vs4  = reinterpret_cast<const float4*>(vs) + c * 4;

    for (int ki = 0; ki < nkb; ki++) {
        int kb = full ? ki : list[ki];
        size_t base = ((size_t)b * SS + kb * 64) * DDIM + h * 64;
        for (int i = tid; i < 4096; i += 256) {
            int j = i >> 6, d = i & 63;
            ks[j * 65 + d] = k[base + (size_t)j * DDIM + d];
            vs[j * 64 + d] = v[base + (size_t)j * DDIM + d];
        }
        __syncthreads();

        float acc[16];
#pragma unroll
        for (int jj = 0; jj < 16; jj++) acc[jj] = 0.f;
#pragma unroll 4
        for (int d = 0; d < 64; d++) {
            float qd = qrow[d];
#pragma unroll
            for (int jj = 0; jj < 16; jj++)
                acc[jj] = fmaf(qd, kbase[jj * 65 + d], acc[jj]);
        }
        float bm = -1e30f;
#pragma unroll
        for (int jj = 0; jj < 16; jj++) {
            acc[jj] *= 0.125f;                 // 1/sqrt(64)
            bm = fmaxf(bm, acc[jj]);
        }
        bm = fmaxf(bm, __shfl_xor_sync(0xffffffffu, bm, 1));
        bm = fmaxf(bm, __shfl_xor_sync(0xffffffffu, bm, 2));
        float mnew = fmaxf(mrun, bm);
        float corr = __expf(mrun - mnew);
        lrun *= corr;
#pragma unroll
        for (int dd = 0; dd < 16; dd++) ctx[dd] *= corr;
        float psum = 0.f;
#pragma unroll
        for (int jj = 0; jj < 16; jj++) {
            float p = __expf(acc[jj] - mnew);
            prow[c * 16 + jj] = p;
            psum += p;
        }
        psum += __shfl_xor_sync(0xffffffffu, psum, 1);
        psum += __shfl_xor_sync(0xffffffffu, psum, 2);
        lrun += psum;
        mrun = mnew;
        __syncwarp();
#pragma unroll 4
        for (int j = 0; j < 64; j++) {
            float p = prow[j];
            float4 v0 = vs4[j * 16 + 0];
            float4 v1 = vs4[j * 16 + 1];
            float4 v2 = vs4[j * 16 + 2];
            float4 v3 = vs4[j * 16 + 3];
            ctx[ 0] = fmaf(p, v0.x, ctx[ 0]); ctx[ 1] = fmaf(p, v0.y, ctx[ 1]);
            ctx[ 2] = fmaf(p, v0.z, ctx[ 2]); ctx[ 3] = fmaf(p, v0.w, ctx[ 3]);
            ctx[ 4] = fmaf(p, v1.x, ctx[ 4]); ctx[ 5] = fmaf(p, v1.y, ctx[ 5]);
            ctx[ 6] = fmaf(p, v1.z, ctx[ 6]); ctx[ 7] = fmaf(p, v1.w, ctx[ 7]);
            ctx[ 8] = fmaf(p, v2.x, ctx[ 8]); ctx[ 9] = fmaf(p, v2.y, ctx[ 9]);
            ctx[10] = fmaf(p, v2.z, ctx[10]); ctx[11] = fmaf(p, v2.w, ctx[11]);
            ctx[12] = fmaf(p, v3.x, ctx[12]); ctx[13] = fmaf(p, v3.y, ctx[13]);
            ctx[14] = fmaf(p, v3.z, ctx[14]); ctx[15] = fmaf(p, v3.w, ctx[15]);
        }
        __syncthreads();
    }
    float inv = 1.f / lrun;
    size_t orow = qbase + (size_t)r * DDIM + c * 16;
#pragma unroll
    for (int d4 = 0; d4 < 4; d4++) {
        float4 ov;
        ov.x = ctx[d4 * 4 + 0] * inv;
        ov.y = ctx[d4 * 4 + 1] * inv;
        ov.z = ctx[d4 * 4 + 2] * inv;
        ov.w = ctx[d4 * 4 + 3] * inv;
        *reinterpret_cast<float4*>(o + orow + d4 * 4) = ov;
    }
}

// ---------------- mean-pool + linear head ----------------
__global__ void pool_kernel(const float* __restrict__ x,
                            const float* __restrict__ w,
                            const float* __restrict__ fb,
                            float* __restrict__ out) {
    int b = blockIdx.x;
    const float* xb = x + (size_t)b * SS * DDIM;
    float wd = w[threadIdx.x];     // blockDim.x == DDIM
    float acc = 0.f;
    for (int s = 0; s < SS; s++)
        acc += xb[(size_t)s * DDIM + threadIdx.x] * wd;
    float2 r = blockReduce2(acc, 0.f);
    if (threadIdx.x == 0)
        out[b] = r.x * (1.f / SS) + fb[0];
}

// ---------------- launch ----------------
extern "C" void kernel_launch(void* const* d_in, const int* in_sizes, int n_in,
                              void* d_out, int out_size) {
    const int*   ids      = (const int*)  d_in[0];
    const int*   rblocks  = (const int*)  d_in[1];
    const float* emb_tok  = (const float*)d_in[2];
    const float* emb_pos  = (const float*)d_in[3];
    const float* ln_emb_g = (const float*)d_in[4];
    const float* ln_emb_b = (const float*)d_in[5];
    const float* Wq = (const float*)d_in[6];
    const float* bq = (const float*)d_in[7];
    const float* Wk = (const float*)d_in[8];
    const float* bk = (const float*)d_in[9];
    const float* Wv = (const float*)d_in[10];
    const float* bv = (const float*)d_in[11];
    const float* Wo = (const float*)d_in[12];
    const float* bo = (const float*)d_in[13];
    const float* ln1_g = (const float*)d_in[14];
    const float* ln1_b = (const float*)d_in[15];
    const float* W1 = (const float*)d_in[16];
    const float* b1 = (const float*)d_in[17];
    const float* W2 = (const float*)d_in[18];
    const float* b2 = (const float*)d_in[19];
    const float* ln2_g = (const float*)d_in[20];
    const float* ln2_b = (const float*)d_in[21];
    const float* fc_w  = (const float*)d_in[22];
    const float* fc_b  = (const float*)d_in[23];
    float* out = (float*)d_out;

    float *x, *q, *k, *v, *t, *ffh;
    cudaGetSymbolAddress((void**)&x,   g_x);
    cudaGetSymbolAddress((void**)&q,   g_q);
    cudaGetSymbolAddress((void**)&k,   g_k);
    cudaGetSymbolAddress((void**)&v,   g_v);
    cudaGetSymbolAddress((void**)&t,   g_t);
    cudaGetSymbolAddress((void**)&ffh, g_ffh);

    const int SMEM_ATTN = (64 * 65 * 3 + 64 * 64) * (int)sizeof(float);  // 66304 B
    cudaFuncSetAttribute(attn_kernel,
                         cudaFuncAttributeMaxDynamicSharedMemorySize, SMEM_ATTN);

    dim3 g768 (DDIM / 64, MM / 128);   // (12, 64)
    dim3 g3072(FF   / 64, MM / 128);   // (48, 64)
    dim3 gatt (NB, HH, BB);            // (64, 12, 2)

    embed_ln_kernel<<<MM, 256>>>(ids, emb_tok, emb_pos, ln_emb_g, ln_emb_b, x);

    for (int l = 0; l < LL; l++) {
        const float* Wq_l = Wq + (size_t)l * DDIM * DDIM;
        const float* Wk_l = Wk + (size_t)l * DDIM * DDIM;
        const float* Wv_l = Wv + (size_t)l * DDIM * DDIM;
        const float* Wo_l = Wo + (size_t)l * DDIM * DDIM;
        const float* W1_l = W1 + (size_t)l * DDIM * FF;
        const float* W2_l = W2 + (size_t)l * FF * DDIM;

        gemm_kernel<0><<<g768, 256>>>(x, Wq_l, bq + l * DDIM, q, DDIM, DDIM);
        gemm_kernel<0><<<g768, 256>>>(x, Wk_l, bk + l * DDIM, k, DDIM, DDIM);
        gemm_kernel<0><<<g768, 256>>>(x, Wv_l, bv + l * DDIM, v, DDIM, DDIM);

        attn_kernel<<<gatt, 256, SMEM_ATTN>>>(q, k, v, rblocks, t);

        gemm_kernel<0><<<g768, 256>>>(t, Wo_l, bo + l * DDIM, q, DDIM, DDIM);
        add_ln_kernel<<<MM, 256>>>(x, q, ln1_g + l * DDIM, ln1_b + l * DDIM);

        gemm_kernel<1><<<g3072, 256>>>(x, W1_l, b1 + l * FF, ffh, FF, DDIM);
        gemm_kernel<0><<<g768, 256>>>(ffh, W2_l, b2 + l * DDIM, q, DDIM, FF);
        add_ln_kernel<<<MM, 256>>>(x, q, ln2_g + l * DDIM, ln2_b + l * DDIM);
    }

    pool_kernel<<<BB, DDIM>>>(x, fc_w, fc_b, out);
}

// round 4
// speedup vs baseline: 2.0249x; 2.0249x over previous
#include <cuda_runtime.h>
#include <math.h>

// ---------------- problem constants ----------------
#define BB   2
#define SS   4096
#define DDIM 768
#define HH   12
#define DH   64
#define NB   64          // S / BLK
#define LL   2
#define MM   (BB*SS)     // 8192 tokens
#define FF   (4*DDIM)    // 3072

// ---------------- persistent scratch (no runtime allocs allowed) ----------------
__device__ float g_x  [MM*DDIM];
__device__ float g_q  [MM*DDIM];
__device__ float g_k  [MM*DDIM];
__device__ float g_v  [MM*DDIM];
__device__ float g_t  [MM*DDIM];
__device__ float g_ffh[MM*FF];
// full-attention split-K partials: slot = (b*2+qi)*12+h  (48 slots), 8 chunks each
__device__ float g_pctx[48*8*64*64];   // [slot][chunk][q][d]  (unnormalized ctx)
__device__ float g_pm  [48*8*64];      // chunk max per q-row
__device__ float g_pl  [48*8*64];      // chunk sum per q-row
__device__ float g_pool[64];           // [b][chunk]

// ---------------- helpers ----------------
__device__ __forceinline__ float2 blockReduce2(float a, float b) {
    __shared__ float sbuf[64];
    const unsigned FULLM = 0xffffffffu;
#pragma unroll
    for (int o = 16; o > 0; o >>= 1) {
        a += __shfl_down_sync(FULLM, a, o);
        b += __shfl_down_sync(FULLM, b, o);
    }
    int warp = threadIdx.x >> 5;
    int nw   = (blockDim.x + 31) >> 5;
    if ((threadIdx.x & 31) == 0) { sbuf[warp] = a; sbuf[32 + warp] = b; }
    __syncthreads();
    if (threadIdx.x == 0) {
        float ta = 0.f, tb = 0.f;
        for (int i = 0; i < nw; i++) { ta += sbuf[i]; tb += sbuf[32 + i]; }
        sbuf[0] = ta; sbuf[32] = tb;
    }
    __syncthreads();
    return make_float2(sbuf[0], sbuf[32]);
}

__device__ __forceinline__ float gelu_tanh(float x) {
    float x3 = x * x * x;
    return 0.5f * x * (1.f + tanhf(0.79788456080286535588f * (x + 0.044715f * x3)));
}

// ---------------- embedding + LN ----------------
__global__ void embed_ln_kernel(const int* __restrict__ ids,
                                const float* __restrict__ emb_tok,
                                const float* __restrict__ emb_pos,
                                const float* __restrict__ g,
                                const float* __restrict__ bta,
                                float* __restrict__ x) {
    int token = blockIdx.x;
    int s = token & (SS - 1);
    int id = ids[token];
    const float* et = emb_tok + (size_t)id * DDIM;
    const float* ep = emb_pos + (size_t)s * DDIM;
    float vals[3];
    float sum = 0.f, sq = 0.f;
#pragma unroll
    for (int i = 0; i < 3; i++) {
        int d = threadIdx.x + i * 256;
        float vv = et[d] + ep[d];
        vals[i] = vv; sum += vv; sq += vv * vv;
    }
    float2 r = blockReduce2(sum, sq);
    float mean = r.x * (1.f / DDIM);
    float var  = r.y * (1.f / DDIM) - mean * mean;
    float rstd = rsqrtf(var + 1e-12f);
    float* xr = x + (size_t)token * DDIM;
#pragma unroll
    for (int i = 0; i < 3; i++) {
        int d = threadIdx.x + i * 256;
        xr[d] = (vals[i] - mean) * rstd * g[d] + bta[d];
    }
}

// ---------------- residual add + LN (in-place on x) ----------------
__global__ void add_ln_kernel(float* __restrict__ x,
                              const float* __restrict__ y,
                              const float* __restrict__ g,
                              const float* __restrict__ bta) {
    int token = blockIdx.x;
    float* xr = x + (size_t)token * DDIM;
    const float* yr = y + (size_t)token * DDIM;
    float vals[3];
    float sum = 0.f, sq = 0.f;
#pragma unroll
    for (int i = 0; i < 3; i++) {
        int d = threadIdx.x + i * 256;
        float vv = xr[d] + yr[d];
        vals[i] = vv; sum += vv; sq += vv * vv;
    }
    float2 r = blockReduce2(sum, sq);
    float mean = r.x * (1.f / DDIM);
    float var  = r.y * (1.f / DDIM) - mean * mean;
    float rstd = rsqrtf(var + 1e-12f);
#pragma unroll
    for (int i = 0; i < 3; i++) {
        int d = threadIdx.x + i * 256;
        xr[d] = (vals[i] - mean) * rstd * g[d] + bta[d];
    }
}

// ---------------- SGEMM body: C[M,N] = A[M,Kd] @ W[Kd,N] + bias --------------
// BM=128, BN=64, BK=16, 256 threads, 8x4 micro-tile, register prefetch pipeline.
template <int DO_GELU>
__device__ __forceinline__ void gemm_body(const float* __restrict__ A,
                                          const float* __restrict__ W,
                                          const float* __restrict__ bias,
                                          float* __restrict__ C,
                                          int N, int Kd) {
    __shared__ float As[16][132];   // transposed A tile (+4 pad)
    __shared__ float Bs[16][64];
    int tid = threadIdx.x;
    int tx = tid & 15, ty = tid >> 4;
    const int m0 = blockIdx.y * 128, n0 = blockIdx.x * 64;
    float acc[8][4];
#pragma unroll
    for (int i = 0; i < 8; i++)
#pragma unroll
        for (int j = 0; j < 4; j++) acc[i][j] = 0.f;

    const float* Aptr = A + (size_t)m0 * Kd;
    const float* Wptr = W + n0;
    const int arow = tid >> 2;
    const int acol = (tid & 3) * 4;
    const int brow = tid >> 4;
    const int bcol = (tid & 15) * 4;

    // prefetch tile 0
    float4 pa0 = *reinterpret_cast<const float4*>(Aptr + (size_t)arow * Kd + acol);
    float4 pa1 = *reinterpret_cast<const float4*>(Aptr + (size_t)(arow + 64) * Kd + acol);
    float4 pb  = *reinterpret_cast<const float4*>(Wptr + (size_t)brow * N + bcol);

    for (int k0 = 0; k0 < Kd; k0 += 16) {
        As[acol + 0][arow]      = pa0.x;
        As[acol + 1][arow]      = pa0.y;
        As[acol + 2][arow]      = pa0.z;
        As[acol + 3][arow]      = pa0.w;
        As[acol + 0][arow + 64] = pa1.x;
        As[acol + 1][arow + 64] = pa1.y;
        As[acol + 2][arow + 64] = pa1.z;
        As[acol + 3][arow + 64] = pa1.w;
        *reinterpret_cast<float4*>(&Bs[brow][bcol]) = pb;
        __syncthreads();

        if (k0 + 16 < Kd) {   // prefetch next tile while computing this one
            pa0 = *reinterpret_cast<const float4*>(Aptr + (size_t)arow * Kd + k0 + 16 + acol);
            pa1 = *reinterpret_cast<const float4*>(Aptr + (size_t)(arow + 64) * Kd + k0 + 16 + acol);
            pb  = *reinterpret_cast<const float4*>(Wptr + (size_t)(k0 + 16 + brow) * N + bcol);
        }
#pragma unroll
        for (int kk = 0; kk < 16; kk++) {
            float a[8], b[4];
#pragma unroll
            for (int i = 0; i < 2; i++) {
                float4 t = *reinterpret_cast<const float4*>(&As[kk][ty * 8 + i * 4]);
                a[i*4+0] = t.x; a[i*4+1] = t.y; a[i*4+2] = t.z; a[i*4+3] = t.w;
            }
            float4 tb = *reinterpret_cast<const float4*>(&Bs[kk][tx * 4]);
            b[0] = tb.x; b[1] = tb.y; b[2] = tb.z; b[3] = tb.w;
#pragma unroll
            for (int i = 0; i < 8; i++)
#pragma unroll
                for (int j = 0; j < 4; j++)
                    acc[i][j] = fmaf(a[i], b[j], acc[i][j]);
        }
        __syncthreads();
    }
    float4 bv = *reinterpret_cast<const float4*>(bias + n0 + tx * 4);
    float bb[4] = {bv.x, bv.y, bv.z, bv.w};
#pragma unroll
    for (int i = 0; i < 8; i++) {
        int row = m0 + ty * 8 + i;
        float4 o;
        o.x = acc[i][0] + bb[0];
        o.y = acc[i][1] + bb[1];
        o.z = acc[i][2] + bb[2];
        o.w = acc[i][3] + bb[3];
        if (DO_GELU) {
            o.x = gelu_tanh(o.x); o.y = gelu_tanh(o.y);
            o.z = gelu_tanh(o.z); o.w = gelu_tanh(o.w);
        }
        *reinterpret_cast<float4*>(C + (size_t)row * N + n0 + tx * 4) = o;
    }
}

template <int DO_GELU>
__global__ void __launch_bounds__(256, 2)
gemm_kernel(const float* __restrict__ A, const float* __restrict__ W,
            const float* __restrict__ bias, float* __restrict__ C,
            int N, int Kd) {
    gemm_body<DO_GELU>(A, W, bias, C, N, Kd);
}

// fused q/k/v: grid.z selects the projection (one launch, 2304 CTAs)
__global__ void __launch_bounds__(256, 2)
gemm_qkv_kernel(const float* __restrict__ A,
                const float* __restrict__ Wq, const float* __restrict__ Wk,
                const float* __restrict__ Wv,
                const float* __restrict__ bq, const float* __restrict__ bk,
                const float* __restrict__ bv,
                float* __restrict__ q, float* __restrict__ k, float* __restrict__ v) {
    const float* W; const float* bias; float* C;
    if (blockIdx.z == 0)      { W = Wq; bias = bq; C = q; }
    else if (blockIdx.z == 1) { W = Wk; bias = bk; C = k; }
    else                      { W = Wv; bias = bv; C = v; }
    gemm_body<0>(A, W, bias, C, DDIM, DDIM);
}

// ---------------- attention core ----------------
// 256 threads. qy = tid>>4 (16 groups of 4 q-rows), kx/dx = tid&15 (4 keys/dims).
// smem (floats): qT[64][68] (d-major), kT[64][68] (d-major), vs[64][68], pT[64][68].
// Processes 8 key blocks with online softmax. Returns ctx (unnormalized), m, l.
#define ATT_PAD 68
#define ATT_TILE (64*ATT_PAD)
#define ATT_SMEM_BYTES (4*ATT_TILE*4)

struct AttnState { float ctx[4][4]; float m[4]; float l[4]; };

__device__ __forceinline__ void attn_compute(const float* __restrict__ k,
                                             const float* __restrict__ v,
                                             const int* list, int b, int h,
                                             float* sm, AttnState& st) {
    float* qT = sm;
    float* kT = sm + ATT_TILE;
    float* vs = sm + 2 * ATT_TILE;
    float* pT = sm + 3 * ATT_TILE;
    int tid = threadIdx.x;
    int qy = tid >> 4, kx = tid & 15;
    const unsigned FULLM = 0xffffffffu;

#pragma unroll
    for (int i = 0; i < 4; i++) {
        st.m[i] = -1e30f; st.l[i] = 0.f;
#pragma unroll
        for (int j = 0; j < 4; j++) st.ctx[i][j] = 0.f;
    }

#pragma unroll 1
    for (int ki = 0; ki < 8; ki++) {
        int kb = list[ki];
        size_t base = ((size_t)b * SS + kb * 64) * DDIM + h * 64;
        __syncthreads();            // prior PV reads done before overwrite
        const float* kg = k + base;
        const float* vg = v + base;
        for (int i = tid; i < 4096; i += 256) {
            int row = i >> 6, d = i & 63;
            float kvval = kg[(size_t)row * DDIM + d];
            kT[d * ATT_PAD + row] = kvval;
            vs[row * ATT_PAD + d] = vg[(size_t)row * DDIM + d];
        }
        __syncthreads();

        // ---- scores: s[4 q][4 k] via float4 reads of transposed tiles ----
        float s[4][4];
#pragma unroll
        for (int i = 0; i < 4; i++)
#pragma unroll
            for (int j = 0; j < 4; j++) s[i][j] = 0.f;
#pragma unroll 4
        for (int d = 0; d < 64; d++) {
            float4 aq = *reinterpret_cast<const float4*>(qT + d * ATT_PAD + qy * 4);
            float4 bk = *reinterpret_cast<const float4*>(kT + d * ATT_PAD + kx * 4);
            float qa[4] = {aq.x, aq.y, aq.z, aq.w};
            float kbv[4] = {bk.x, bk.y, bk.z, bk.w};
#pragma unroll
            for (int i = 0; i < 4; i++)
#pragma unroll
                for (int j = 0; j < 4; j++)
                    s[i][j] = fmaf(qa[i], kbv[j], s[i][j]);
        }

        // ---- online softmax per q-row (reduce over 16 kx lanes via shfl) ----
        float p[4][4];
#pragma unroll
        for (int i = 0; i < 4; i++) {
            float rmax = -1e30f;
#pragma unroll
            for (int j = 0; j < 4; j++) {
                s[i][j] *= 0.125f;                    // 1/sqrt(64)
                rmax = fmaxf(rmax, s[i][j]);
            }
            rmax = fmaxf(rmax, __shfl_xor_sync(FULLM, rmax, 1));
            rmax = fmaxf(rmax, __shfl_xor_sync(FULLM, rmax, 2));
            rmax = fmaxf(rmax, __shfl_xor_sync(FULLM, rmax, 4));
            rmax = fmaxf(rmax, __shfl_xor_sync(FULLM, rmax, 8));
            float mnew = fmaxf(st.m[i], rmax);
            float corr = __expf(st.m[i] - mnew);
            float psum = 0.f;
#pragma unroll
            for (int j = 0; j < 4; j++) {
                p[i][j] = __expf(s[i][j] - mnew);
                psum += p[i][j];
            }
            psum += __shfl_xor_sync(FULLM, psum, 1);
            psum += __shfl_xor_sync(FULLM, psum, 2);
            psum += __shfl_xor_sync(FULLM, psum, 4);
            psum += __shfl_xor_sync(FULLM, psum, 8);
            st.l[i] = st.l[i] * corr + psum;
            st.m[i] = mnew;
#pragma unroll
            for (int j = 0; j < 4; j++) st.ctx[i][j] *= corr;
        }
        // store p transposed: pT[k][q] so PV can read float4 over q-rows
#pragma unroll
        for (int j = 0; j < 4; j++) {
            float4 pv = make_float4(p[0][j], p[1][j], p[2][j], p[3][j]);
            *reinterpret_cast<float4*>(pT + (kx * 4 + j) * ATT_PAD + qy * 4) = pv;
        }
        __syncwarp();    // pT exchange is intra-half-warp (same qy group)

        // ---- PV: ctx[4 q][4 d] over 64 keys ----
#pragma unroll 4
        for (int kk2 = 0; kk2 < 64; kk2++) {
            float4 p4 = *reinterpret_cast<const float4*>(pT + kk2 * ATT_PAD + qy * 4);
            float4 v4 = *reinterpret_cast<const float4*>(vs + kk2 * ATT_PAD + kx * 4);
            float pa[4] = {p4.x, p4.y, p4.z, p4.w};
            float va[4] = {v4.x, v4.y, v4.z, v4.w};
#pragma unroll
            for (int i = 0; i < 4; i++)
#pragma unroll
                for (int j = 0; j < 4; j++)
                    st.ctx[i][j] = fmaf(pa[i], va[j], st.ctx[i][j]);
        }
    }
}

// sparse blocks: grid (62, 12, 2), qb = x+1
__global__ void __launch_bounds__(256)
attn_sparse_kernel(const float* __restrict__ q, const float* __restrict__ k,
                   const float* __restrict__ v, const int* __restrict__ rand_blocks,
                   float* __restrict__ o) {
    extern __shared__ float sm[];
    int qb = blockIdx.x + 1, h = blockIdx.y, b = blockIdx.z;
    int tid = threadIdx.x;
    int qy = tid >> 4, dx = tid & 15;
    size_t qbase = ((size_t)b * SS + qb * 64) * DDIM + h * 64;

    for (int i = tid; i < 4096; i += 256) {
        int row = i >> 6, d = i & 63;
        sm[d * ATT_PAD + row] = q[qbase + (size_t)row * DDIM + d];
    }
    const int* rb = rand_blocks + ((size_t)h * NB + qb) * 3;
    int list[8];
    list[0] = 0; list[1] = qb - 1; list[2] = qb; list[3] = qb + 1;
    list[4] = NB - 1; list[5] = rb[0]; list[6] = rb[1]; list[7] = rb[2];

    AttnState st;
    attn_compute(k, v, list, b, h, sm, st);

#pragma unroll
    for (int i = 0; i < 4; i++) {
        float inv = 1.f / st.l[i];
        float4 ov = make_float4(st.ctx[i][0] * inv, st.ctx[i][1] * inv,
                                st.ctx[i][2] * inv, st.ctx[i][3] * inv);
        *reinterpret_cast<float4*>(o + qbase + (size_t)(qy * 4 + i) * DDIM + dx * 4) = ov;
    }
}

// full rows, split-K: grid (8 chunks, 12 h, 4 = b*2+qi). Writes partials.
__global__ void __launch_bounds__(256)
attn_full_kernel(const float* __restrict__ q, const float* __restrict__ k,
                 const float* __restrict__ v) {
    extern __shared__ float sm[];
    int chunk = blockIdx.x, h = blockIdx.y;
    int b = blockIdx.z >> 1, qi = blockIdx.z & 1;
    int qb = qi ? (NB - 1) : 0;
    int tid = threadIdx.x;
    int qy = tid >> 4, dx = tid & 15;
    size_t qbase = ((size_t)b * SS + qb * 64) * DDIM + h * 64;

    for (int i = tid; i < 4096; i += 256) {
        int row = i >> 6, d = i & 63;
        sm[d * ATT_PAD + row] = q[qbase + (size_t)row * DDIM + d];
    }
    int list[8];
#pragma unroll
    for (int i = 0; i < 8; i++) list[i] = chunk * 8 + i;

    AttnState st;
    attn_compute(k, v, list, b, h, sm, st);

    int slot = (b * 2 + qi) * 12 + h;
    int pidx = slot * 8 + chunk;
    float* pc = g_pctx + (size_t)pidx * 4096;
#pragma unroll
    for (int i = 0; i < 4; i++) {
        int row = qy * 4 + i;
        float4 ov = make_float4(st.ctx[i][0], st.ctx[i][1], st.ctx[i][2], st.ctx[i][3]);
        *reinterpret_cast<float4*>(pc + row * 64 + dx * 4) = ov;
        if (dx == 0) {
            g_pm[pidx * 64 + row] = st.m[i];
            g_pl[pidx * 64 + row] = st.l[i];
        }
    }
}

// merge the 8 chunks per full row: grid (48), 256 threads
__global__ void __launch_bounds__(256)
attn_merge_kernel(float* __restrict__ o) {
    int slot = blockIdx.x;
    int h = slot % 12;
    int t = slot / 12;
    int qi = t & 1, b = t >> 1;
    int qb = qi ? (NB - 1) : 0;
    int tid = threadIdx.x;
    int r = tid >> 2, cg = tid & 3;

    float M = -1e30f;
#pragma unroll
    for (int c = 0; c < 8; c++)
        M = fmaxf(M, g_pm[(slot * 8 + c) * 64 + r]);
    float w[8]; float L = 0.f;
#pragma unroll
    for (int c = 0; c < 8; c++) {
        w[c] = __expf(g_pm[(slot * 8 + c) * 64 + r] - M);
        L += g_pl[(slot * 8 + c) * 64 + r] * w[c];
    }
    float invL = 1.f / L;
    size_t obase = ((size_t)b * SS + qb * 64 + r) * DDIM + h * 64;
#pragma unroll
    for (int d4 = 0; d4 < 4; d4++) {
        int d = cg * 16 + d4 * 4;
        float acc[4] = {0.f, 0.f, 0.f, 0.f};
#pragma unroll
        for (int c = 0; c < 8; c++) {
            const float4 cv = *reinterpret_cast<const float4*>(
                g_pctx + (size_t)(slot * 8 + c) * 4096 + r * 64 + d);
            acc[0] = fmaf(cv.x, w[c], acc[0]);
            acc[1] = fmaf(cv.y, w[c], acc[1]);
            acc[2] = fmaf(cv.z, w[c], acc[2]);
            acc[3] = fmaf(cv.w, w[c], acc[3]);
        }
        float4 ov = make_float4(acc[0] * invL, acc[1] * invL, acc[2] * invL, acc[3] * invL);
        *reinterpret_cast<float4*>(o + obase + d) = ov;
    }
}

// ---------------- mean-pool + linear head (two-stage, deterministic) --------
__global__ void pool1_kernel(const float* __restrict__ x, const float* __restrict__ w) {
    int b = blockIdx.x, chunk = blockIdx.y;       // 32 chunks of 128 rows
    const float* xb = x + ((size_t)b * SS + chunk * 128) * DDIM;
    float wd = w[threadIdx.x];                    // blockDim.x == 768
    float acc = 0.f;
    for (int s = 0; s < 128; s++)
        acc += xb[(size_t)s * DDIM + threadIdx.x] * wd;
    float2 r = blockReduce2(acc, 0.f);
    if (threadIdx.x == 0) g_pool[b * 32 + chunk] = r.x;
}

__global__ void pool2_kernel(const float* __restrict__ fb, float* __restrict__ out) {
    int b = threadIdx.x;
    if (b < BB) {
        float s = 0.f;
        for (int c = 0; c < 32; c++) s += g_pool[b * 32 + c];
        out[b] = s * (1.f / SS) + fb[0];
    }
}

// ---------------- launch ----------------
extern "C" void kernel_launch(void* const* d_in, const int* in_sizes, int n_in,
                              void* d_out, int out_size) {
    const int*   ids      = (const int*)  d_in[0];
    const int*   rblocks  = (const int*)  d_in[1];
    const float* emb_tok  = (const float*)d_in[2];
    const float* emb_pos  = (const float*)d_in[3];
    const float* ln_emb_g = (const float*)d_in[4];
    const float* ln_emb_b = (const float*)d_in[5];
    const float* Wq = (const float*)d_in[6];
    const float* bq = (const float*)d_in[7];
    const float* Wk = (const float*)d_in[8];
    const float* bk = (const float*)d_in[9];
    const float* Wv = (const float*)d_in[10];
    const float* bv = (const float*)d_in[11];
    const float* Wo = (const float*)d_in[12];
    const float* bo = (const float*)d_in[13];
    const float* ln1_g = (const float*)d_in[14];
    const float* ln1_b = (const float*)d_in[15];
    const float* W1 = (const float*)d_in[16];
    const float* b1 = (const float*)d_in[17];
    const float* W2 = (const float*)d_in[18];
    const float* b2 = (const float*)d_in[19];
    const float* ln2_g = (const float*)d_in[20];
    const float* ln2_b = (const float*)d_in[21];
    const float* fc_w  = (const float*)d_in[22];
    const float* fc_b  = (const float*)d_in[23];
    float* out = (float*)d_out;

    float *x, *q, *k, *v, *t, *ffh;
    cudaGetSymbolAddress((void**)&x,   g_x);
    cudaGetSymbolAddress((void**)&q,   g_q);
    cudaGetSymbolAddress((void**)&k,   g_k);
    cudaGetSymbolAddress((void**)&v,   g_v);
    cudaGetSymbolAddress((void**)&t,   g_t);
    cudaGetSymbolAddress((void**)&ffh, g_ffh);

    cudaFuncSetAttribute(attn_sparse_kernel,
                         cudaFuncAttributeMaxDynamicSharedMemorySize, ATT_SMEM_BYTES);
    cudaFuncSetAttribute(attn_full_kernel,
                         cudaFuncAttributeMaxDynamicSharedMemorySize, ATT_SMEM_BYTES);

    dim3 gqkv(DDIM / 64, MM / 128, 3);   // (12, 64, 3)
    dim3 g768 (DDIM / 64, MM / 128);     // (12, 64)
    dim3 g3072(FF   / 64, MM / 128);     // (48, 64)
    dim3 gspr (NB - 2, HH, BB);          // (62, 12, 2)
    dim3 gful (8, HH, 2 * BB);           // (8, 12, 4)

    embed_ln_kernel<<<MM, 256>>>(ids, emb_tok, emb_pos, ln_emb_g, ln_emb_b, x);

    for (int l = 0; l < LL; l++) {
        const float* Wq_l = Wq + (size_t)l * DDIM * DDIM;
        const float* Wk_l = Wk + (size_t)l * DDIM * DDIM;
        const float* Wv_l = Wv + (size_t)l * DDIM * DDIM;
        const float* Wo_l = Wo + (size_t)l * DDIM * DDIM;
        const float* W1_l = W1 + (size_t)l * DDIM * FF;
        const float* W2_l = W2 + (size_t)l * FF * DDIM;

        gemm_qkv_kernel<<<gqkv, 256>>>(x, Wq_l, Wk_l, Wv_l,
                                       bq + l * DDIM, bk + l * DDIM, bv + l * DDIM,
                                       q, k, v);

        attn_sparse_kernel<<<gspr, 256, ATT_SMEM_BYTES>>>(q, k, v, rblocks, t);
        attn_full_kernel  <<<gful, 256, ATT_SMEM_BYTES>>>(q, k, v);
        attn_merge_kernel <<<48, 256>>>(t);

        gemm_kernel<0><<<g768, 256>>>(t, Wo_l, bo + l * DDIM, q, DDIM, DDIM);
        add_ln_kernel<<<MM, 256>>>(x, q, ln1_g + l * DDIM, ln1_b + l * DDIM);

        gemm_kernel<1><<<g3072, 256>>>(x, W1_l, b1 + l * FF, ffh, FF, DDIM);
        gemm_kernel<0><<<g768, 256>>>(ffh, W2_l, b2 + l * DDIM, q, DDIM, FF);
        add_ln_kernel<<<MM, 256>>>(x, q, ln2_g + l * DDIM, ln2_b + l * DDIM);
    }

    pool1_kernel<<<dim3(BB, 32), DDIM>>>(x, fc_w);
    pool2_kernel<<<1, 32>>>(fc_b, out);
}